// round 4
// baseline (speedup 1.0000x reference)
#include <cuda_runtime.h>
#include <math.h>

// ---------------------------------------------------------------------------
// CondRotConv2d: B=16, Cin=32, Cout=32, E=8, K=3, H=W=256
//   1) avg[b,ci]  = mean over HxW
//   2) gate/theta = sigmoid(avg @ W^T + b)      [B,8]
//   3) A[b,e,9,9] = gate * rotation_matrix(theta)
//   4) wout[b,co,ci,9] = sum_e sum_j A[b,e,k,j] * weight[e,co,ci,j]
//   5) out[b,co,h,w] = 3x3 cross-correlation of x[b] with wout[b,co], pad 1
// Conv: packed fma.rn.f32x2 + software-pipelined global->reg->smem loads.
// ---------------------------------------------------------------------------

#define B_    16
#define CIN_  32
#define COUT_ 32
#define E_    8
#define HW_   256

typedef unsigned long long u64;

__device__ __forceinline__ u64 pack2(float lo, float hi) {
    u64 r; asm("mov.b64 %0, {%1, %2};" : "=l"(r) : "f"(lo), "f"(hi)); return r;
}
__device__ __forceinline__ u64 fma2(u64 a, u64 b, u64 c) {
    u64 d; asm("fma.rn.f32x2 %0, %1, %2, %3;" : "=l"(d) : "l"(a), "l"(b), "l"(c)); return d;
}
__device__ __forceinline__ void unpack2(u64 v, float& lo, float& hi) {
    asm("mov.b64 {%0, %1}, %2;" : "=f"(lo), "=f"(hi) : "l"(v));
}

// scratch (device globals: no allocation allowed)
__device__ float g_avg[B_ * CIN_];                  // 512
__device__ float g_wout[B_ * COUT_ * CIN_ * 9];     // 147456

// ---------------------------------------------------------------------------
// Kernel 1: per-(b,ci) mean over 256x256
// ---------------------------------------------------------------------------
__global__ void mean_kernel(const float* __restrict__ x)
{
    int bc = blockIdx.x;                            // 0..511
    const float4* p = (const float4*)(x + (size_t)bc * (HW_ * HW_));
    float s = 0.f;
    for (int i = threadIdx.x; i < (HW_ * HW_) / 4; i += 256) {
        float4 v = p[i];
        s += v.x + v.y + v.z + v.w;
    }
    __shared__ float red[256];
    red[threadIdx.x] = s;
    __syncthreads();
    for (int off = 128; off > 0; off >>= 1) {
        if (threadIdx.x < off) red[threadIdx.x] += red[threadIdx.x + off];
        __syncthreads();
    }
    if (threadIdx.x == 0)
        g_avg[bc] = red[0] * (1.0f / (HW_ * HW_));
}

// ---------------------------------------------------------------------------
// Kernel 2: gate/theta -> rotation matrices -> combined per-sample weights
// ---------------------------------------------------------------------------
__global__ void weight_kernel(const float* __restrict__ weight,
                              const float* __restrict__ fa_w,
                              const float* __restrict__ fa_b,
                              const float* __restrict__ ft_w,
                              const float* __restrict__ ft_b)
{
    int b = blockIdx.x;
    int tid = threadIdx.x;

    __shared__ float s_avg[CIN_];
    __shared__ float s_gate[E_];
    __shared__ float s_theta[E_];
    __shared__ float sA[E_ * 81];

    if (tid < CIN_) s_avg[tid] = g_avg[b * CIN_ + tid];
    __syncthreads();

    if (tid < 16) {
        int e = tid & 7;
        const float* w = (tid < 8) ? fa_w : ft_w;
        float d = (tid < 8) ? fa_b[e] : ft_b[e];
        for (int i = 0; i < CIN_; i++) d += s_avg[i] * w[e * CIN_ + i];
        float sg = 1.0f / (1.0f + expf(-d));        // PROPORTION = 1.0
        if (tid < 8) s_gate[e] = sg; else s_theta[e] = sg;
    }
    __syncthreads();

    // A[e][k][j] = gate * tent(src_r - R_j) * tent(src_c - C_j)
    for (int idx = tid; idx < E_ * 81; idx += 256) {
        int e = idx / 81, kj = idx % 81, k = kj / 9, j = kj % 9;
        float th = s_theta[e];
        float cs = cosf(th), sn = sinf(th);
        float Rk = (float)(k / 3 - 1), Ck = (float)(k % 3 - 1);
        float Rj = (float)(j / 3 - 1), Cj = (float)(j % 3 - 1);
        float sr = cs * Rk - sn * Ck;
        float sc = sn * Rk + cs * Ck;
        float wr = fmaxf(0.f, 1.f - fabsf(sr - Rj));
        float wc = fmaxf(0.f, 1.f - fabsf(sc - Cj));
        sA[idx] = s_gate[e] * wr * wc;
    }
    __syncthreads();

    // wout[b][c][k] = sum_e sum_j A[e][k][j] * weight[e][c][j],  c = co*CIN+ci
    for (int i = 0; i < 4; i++) {
        int c = tid + i * 256;                      // 0..1023
        float acc[9] = {0,0,0,0,0,0,0,0,0};
        for (int e = 0; e < E_; e++) {
            const float* wp = weight + ((size_t)e * (COUT_ * CIN_) + c) * 9;
            float wj[9];
            #pragma unroll
            for (int j = 0; j < 9; j++) wj[j] = wp[j];
            const float* Ae = &sA[e * 81];
            #pragma unroll
            for (int k = 0; k < 9; k++) {
                float a = acc[k];
                #pragma unroll
                for (int j = 0; j < 9; j++) a = fmaf(Ae[k * 9 + j], wj[j], a);
                acc[k] = a;
            }
        }
        float* op = g_wout + (size_t)b * (COUT_ * CIN_ * 9) + (size_t)c * 9;
        #pragma unroll
        for (int k = 0; k < 9; k++) op[k] = acc[k];
    }
}

// ---------------------------------------------------------------------------
// Kernel 3: direct 3x3 conv, per-sample weights, packed f32x2 math,
// software-pipelined loads.
// Block = 256 threads: 32(w) x 8(h) output tile, ALL 32 co.
// Thread: 8 co x 4 adjacent pixels = 8 x 2 packed accumulators.
// ci in 4 chunks of 8; chunk c+1's x/weights prefetched into registers while
// chunk c computes. x tile stride 36 floats (16B-aligned rows, conflict-free:
// bank shift 36 mod 32 = 4 permutes the 8-lane LDS.128 phase).
// ---------------------------------------------------------------------------
#define XLD 11   // ceil(8*340 / 256)
#define WLD 9    // 32*72 / 256

__global__ __launch_bounds__(256, 2)
void conv_kernel(const float* __restrict__ x, float* __restrict__ out)
{
    __shared__ float xs[8][10][36];     // [ci][row][col], 16B-aligned rows
    __shared__ u64   ws2[32][8][10];    // [co][ci][9 pad 10] duplicated pairs

    int b    = blockIdx.y;
    int tile = blockIdx.x;              // 256 tiles: 8 across x 32 down
    int tx = (tile & 7) * 32;
    int ty = (tile >> 3) * 8;

    int tid = threadIdx.x;
    int cg  = tid >> 6;                 // 0..3 : co group of 8
    int t   = tid & 63;
    int py  = t >> 3;                   // 0..7
    int px  = (t & 7) * 4;              // 0,4,...,28

    u64 acc[8][2];
    u64 zero = pack2(0.f, 0.f);
    #pragma unroll
    for (int i = 0; i < 8; i++) { acc[i][0] = zero; acc[i][1] = zero; }

    const float* xb = x + (size_t)b * CIN_ * (HW_ * HW_);
    const float* wb = g_wout + (size_t)b * (COUT_ * CIN_ * 9);

    float xr[XLD];                      // prefetch regs: x tile
    float wr[WLD];                      // prefetch regs: weights

    // ---- prefetch chunk 0 ----
    {
        const int chunk = 0;
        #pragma unroll
        for (int i = 0; i < XLD; i++) {
            int idx = tid + i * 256;
            float v = 0.f;
            if (idx < 8 * 340) {
                int ci  = idx / 340;
                int rem = idx % 340;
                int r = rem / 34, c2 = rem % 34;
                int gy = ty + r - 1, gx = tx + c2 - 1;
                if (gy >= 0 && gy < HW_ && gx >= 0 && gx < HW_)
                    v = xb[((size_t)(chunk * 8 + ci)) * (HW_ * HW_) + gy * HW_ + gx];
            }
            xr[i] = v;
        }
        #pragma unroll
        for (int i = 0; i < WLD; i++) {
            int idx = tid + i * 256;    // always < 2304
            int co  = idx / 72;
            int rem = idx % 72;
            int ci = rem / 9, k = rem % 9;
            wr[i] = wb[((size_t)co * CIN_ + chunk * 8 + ci) * 9 + k];
        }
    }

    for (int chunk = 0; chunk < 4; chunk++) {
        __syncthreads();                // previous compute finished with smem
        // ---- commit prefetched regs to smem ----
        #pragma unroll
        for (int i = 0; i < XLD; i++) {
            int idx = tid + i * 256;
            if (idx < 8 * 340) {
                int ci  = idx / 340;
                int rem = idx % 340;
                xs[ci][rem / 34][rem % 34] = xr[i];
            }
        }
        #pragma unroll
        for (int i = 0; i < WLD; i++) {
            int idx = tid + i * 256;
            int co  = idx / 72;
            int rem = idx % 72;
            ws2[co][rem / 9][rem % 9] = pack2(wr[i], wr[i]);
        }
        __syncthreads();

        // ---- prefetch chunk+1 (LDGs fly during compute below) ----
        if (chunk < 3) {
            int nc = chunk + 1;
            #pragma unroll
            for (int i = 0; i < XLD; i++) {
                int idx = tid + i * 256;
                float v = 0.f;
                if (idx < 8 * 340) {
                    int ci  = idx / 340;
                    int rem = idx % 340;
                    int r = rem / 34, c2 = rem % 34;
                    int gy = ty + r - 1, gx = tx + c2 - 1;
                    if (gy >= 0 && gy < HW_ && gx >= 0 && gx < HW_)
                        v = xb[((size_t)(nc * 8 + ci)) * (HW_ * HW_) + gy * HW_ + gx];
                }
                xr[i] = v;
            }
            #pragma unroll
            for (int i = 0; i < WLD; i++) {
                int idx = tid + i * 256;
                int co  = idx / 72;
                int rem = idx % 72;
                wr[i] = wb[((size_t)co * CIN_ + nc * 8 + rem / 9) * 9 + rem % 9];
            }
        }

        // ---- compute ----
        #pragma unroll
        for (int ci = 0; ci < 8; ci++) {
            u64 xp[3][5];
            #pragma unroll
            for (int r = 0; r < 3; r++) {
                const float* row = &xs[ci][py + r][px];     // 16B-aligned
                float4 v4 = *(const float4*)row;            // cols 0..3
                float2 v2 = *(const float2*)(row + 4);      // cols 4..5
                xp[r][0] = pack2(v4.x, v4.y);
                xp[r][1] = pack2(v4.y, v4.z);
                xp[r][2] = pack2(v4.z, v4.w);
                xp[r][3] = pack2(v4.w, v2.x);
                xp[r][4] = pack2(v2.x, v2.y);
            }

            #pragma unroll
            for (int col = 0; col < 8; col++) {
                const u64* wp = &ws2[cg * 8 + col][ci][0];  // broadcast LDS
                u64 w[9];
                #pragma unroll
                for (int k = 0; k < 9; k++) w[k] = wp[k];

                u64 a0 = acc[col][0], a1 = acc[col][1];
                #pragma unroll
                for (int r = 0; r < 3; r++) {
                    #pragma unroll
                    for (int c = 0; c < 3; c++) {
                        u64 wk = w[r * 3 + c];
                        a0 = fma2(wk, xp[r][c],     a0);    // pixels 0,1
                        a1 = fma2(wk, xp[r][c + 2], a1);    // pixels 2,3
                    }
                }
                acc[col][0] = a0; acc[col][1] = a1;
            }
        }
    }

    // ---- write 8 co x 4 px per thread, vectorized ----
    #pragma unroll
    for (int col = 0; col < 8; col++) {
        int co = cg * 8 + col;
        float4 v;
        unpack2(acc[col][0], v.x, v.y);
        unpack2(acc[col][1], v.z, v.w);
        *(float4*)(out + (((size_t)(b * COUT_ + co)) * HW_ + (ty + py)) * HW_ + tx + px) = v;
    }
}

// ---------------------------------------------------------------------------
extern "C" void kernel_launch(void* const* d_in, const int* in_sizes, int n_in,
                              void* d_out, int out_size)
{
    const float* x    = (const float*)d_in[0];
    const float* wgt  = (const float*)d_in[1];
    const float* fa_w = (const float*)d_in[2];
    const float* fa_b = (const float*)d_in[3];
    const float* ft_w = (const float*)d_in[4];
    const float* ft_b = (const float*)d_in[5];
    float* out = (float*)d_out;

    mean_kernel<<<B_ * CIN_, 256>>>(x);
    weight_kernel<<<B_, 256>>>(wgt, fa_w, fa_b, ft_w, ft_b);
    conv_kernel<<<dim3(256, B_), 256>>>(x, out);
}